// round 10
// baseline (speedup 1.0000x reference)
#include <cuda_runtime.h>
#include <cuda_bf16.h>
#include <cstdint>

#define NUM_EXPERTS 64
#define TOPK 2
#define CAP 128
#define BATCH 8
#define SEQ 4096
#define HID 4096
#define M_TOKENS (BATCH * SEQ)                 /* 32768 */
#define BSE ((size_t)M_TOKENS * NUM_EXPERTS)   /* 2097152 */

/* ------------ device scratch (static, allocation-free) ------------- */
__device__ int             g_sidx[M_TOKENS * TOPK];
__device__ float           g_sw[M_TOKENS * TOPK];
__device__ double          g_acc[2];                 /* aux, z */
__device__ __nv_bfloat16   g_whi[NUM_EXPERTS * HID];
__device__ __nv_bfloat16   g_wlo[NUM_EXPERTS * HID];

/* ---------------------- helpers ------------------------------------ */
__device__ __forceinline__ uint32_t smem_u32(const void* p) {
    uint32_t a;
    asm("{ .reg .u64 t; cvta.to.shared.u64 t, %1; cvt.u32.u64 %0, t; }"
        : "=r"(a) : "l"(p));
    return a;
}
__device__ __forceinline__ void ldsm4(uint32_t* r, uint32_t addr) {
    asm volatile("ldmatrix.sync.aligned.m8n8.x4.shared.b16 {%0,%1,%2,%3}, [%4];"
        : "=r"(r[0]), "=r"(r[1]), "=r"(r[2]), "=r"(r[3]) : "r"(addr));
}
__device__ __forceinline__ void mma_bf16(float* d, const uint32_t* a,
                                         uint32_t b0, uint32_t b1) {
    asm volatile(
        "mma.sync.aligned.m16n8k16.row.col.f32.bf16.bf16.f32 "
        "{%0,%1,%2,%3}, {%4,%5,%6,%7}, {%8,%9}, {%0,%1,%2,%3};"
        : "+f"(d[0]), "+f"(d[1]), "+f"(d[2]), "+f"(d[3])
        : "r"(a[0]), "r"(a[1]), "r"(a[2]), "r"(a[3]), "r"(b0), "r"(b1));
}
__device__ __forceinline__ void cp16(uint32_t dst, const void* src) {
    asm volatile("cp.async.cg.shared.global [%0], [%1], 16;"
                 :: "r"(dst), "l"(src) : "memory");
}
__device__ __forceinline__ void cvt_hl(float a, float b, uint32_t& h, uint32_t& l) {
    __nv_bfloat162 hh = __float22bfloat162_rn(make_float2(a, b));
    float2 hf = __bfloat1622float2(hh);
    __nv_bfloat162 ll = __float22bfloat162_rn(make_float2(a - hf.x, b - hf.y));
    h = *(uint32_t*)&hh;
    l = *(uint32_t*)&ll;
}

/* ============ K0: zero dispatch/combine + split weights ============= */
__global__ void prep_kernel(const float* __restrict__ w, float4* dc) {
    int t = blockIdx.x * 256 + threadIdx.x;           /* grid 2048 */
    const size_t n4 = (2 * BSE) / 4;
    float4 z = make_float4(0.f, 0.f, 0.f, 0.f);
    for (size_t j = t; j < n4; j += 2048 * 256) dc[j] = z;
    int i0 = t * 2;
    if (i0 < NUM_EXPERTS * HID) {
#pragma unroll
        for (int u = 0; u < 2; u++) {
            int i = i0 + u;
            float x = w[i];
            __nv_bfloat16 h = __float2bfloat16(x);
            g_whi[i] = h;
            g_wlo[i] = __float2bfloat16(x - __bfloat162float(h));
        }
    }
    if (t == 0) { g_acc[0] = 0.0; g_acc[1] = 0.0; }
}

/* ===== K1: HMMA bf16-split GEMM (R6 skeleton + A double-buffer) ===== */
/* CTA: 128 tokens x 64 experts, 8 warps (16 rows each), K-chunk 64.
 * A: LDG reg-prefetch -> cvt+STS AFTER MMA (overlaps tensor drain),
 *    2 smem stages.  W: cp.async hi/lo, 2 stages.  1 barrier/chunk.   */
#define TM 128
#define KCH 64
#define NCH (HID / KCH)            /* 64 */
#define RS 144                     /* bytes per 64-bf16 row, padded    */
#define A_LO  18432                /* 128*144 : lo plane within stage  */
#define A_STG 36864                /* hi+lo per stage                  */
#define OFF_W 73728
#define W_LO  9216                 /* 64*144                           */
#define W_STG 18432
#define SMEM_GEMM (OFF_W + 2 * W_STG)   /* 110592 -> occupancy 2 */

__device__ __forceinline__ void cp_w(uint32_t wb, int k0, int wrow, int wkq) {
    const __nv_bfloat16* gh = g_whi + (size_t)wrow * HID + k0 + 16 * wkq;
    const __nv_bfloat16* gl = g_wlo + (size_t)wrow * HID + k0 + 16 * wkq;
    uint32_t off = wrow * RS + 32 * wkq;
    cp16(wb + off,             gh);
    cp16(wb + off + 16,        gh + 8);
    cp16(wb + W_LO + off,      gl);
    cp16(wb + W_LO + off + 16, gl + 8);
}

__global__ void __launch_bounds__(256, 2)
gemm_kernel(const float* __restrict__ hidden, float* __restrict__ probs) {
    extern __shared__ char smem[];
    const uint32_t sb = smem_u32(smem);
    const int tid = threadIdx.x;
    const int lane = tid & 31, wid = tid >> 5;
    const int base = blockIdx.x * TM;
    const int R = wid * 16;

    float acc[32];
#pragma unroll
    for (int i = 0; i < 32; i++) acc[i] = 0.f;

    const int hrow = tid >> 4, hkq = tid & 15;       /* hidden ldg map  */
    const int wrow = tid >> 2, wkq = tid & 3;        /* weight cp map   */
    const float* hp = hidden + (size_t)(base + hrow) * HID + 4 * hkq;
    const uint32_t asts = hrow * RS + 8 * hkq;       /* STS base (row0) */

    float4 h[8];
    /* ---- prologue: chunk0 LDG -> STS stage0; W0 cp; chunk1 LDG ---- */
#pragma unroll
    for (int p = 0; p < 8; p++)
        h[p] = __ldg((const float4*)(hp + (size_t)16 * p * HID));
    cp_w(sb + OFF_W, 0, wrow, wkq);
    asm volatile("cp.async.commit_group;" ::: "memory");
#pragma unroll
    for (int p = 0; p < 8; p++) {
        uint32_t h0, l0, h1, l1;
        cvt_hl(h[p].x, h[p].y, h0, l0);
        cvt_hl(h[p].z, h[p].w, h1, l1);
        uint32_t off = asts + (16 * p) * RS;
        *(uint2*)(smem + off)        = make_uint2(h0, h1);
        *(uint2*)(smem + A_LO + off) = make_uint2(l0, l1);
    }
#pragma unroll
    for (int p = 0; p < 8; p++)
        h[p] = __ldg((const float4*)(hp + KCH + (size_t)16 * p * HID));

    /* ldsm per-lane bases */
    const uint32_t aB = sb + (R + (lane & 15)) * RS + 16 * (lane >> 4);
    const uint32_t bB = sb + OFF_W + (8 * (lane >> 4) + (lane & 7)) * RS
                        + 16 * ((lane >> 3) & 1);

    for (int c = 0; c < NCH; c++) {
        const int s = c & 1;
        asm volatile("cp.async.wait_group 0;" ::: "memory");
        __syncthreads();              /* A(c), W(c) visible; s^1 free  */

        if (c + 1 < NCH) {            /* cp W(c+1) into free stage     */
            cp_w(sb + OFF_W + (s ^ 1) * W_STG, (c + 1) * KCH, wrow, wkq);
            asm volatile("cp.async.commit_group;" ::: "memory");
        }

        /* ---- MMA over stage s ---- */
        const uint32_t aS = aB + s * A_STG;
        const uint32_t bS = bB + s * W_STG;
#pragma unroll
        for (int q = 0; q < 4; q++) {
            uint32_t ah[4], al[4];
            ldsm4(ah, aS + 32 * q);
            ldsm4(al, aS + A_LO + 32 * q);
#pragma unroll
            for (int jp = 0; jp < 4; jp++) {
                uint32_t bh[4], bl[4];
                ldsm4(bh, bS + jp * (16 * RS) + 32 * q);
                ldsm4(bl, bS + W_LO + jp * (16 * RS) + 32 * q);
                mma_bf16(acc + 8 * jp,     ah, bh[0], bh[1]);
                mma_bf16(acc + 8 * jp,     al, bh[0], bh[1]);
                mma_bf16(acc + 8 * jp,     ah, bl[0], bl[1]);
                mma_bf16(acc + 8 * jp + 4, ah, bh[2], bh[3]);
                mma_bf16(acc + 8 * jp + 4, al, bh[2], bh[3]);
                mma_bf16(acc + 8 * jp + 4, ah, bl[2], bl[3]);
            }
        }

        /* ---- cvt+STS A(c+1) into stage s^1 (overlaps MMA drain) ---- */
        if (c + 1 < NCH) {
            uint32_t ab = (s ^ 1) * A_STG + asts;
#pragma unroll
            for (int p = 0; p < 8; p++) {
                uint32_t h0, l0, h1, l1;
                cvt_hl(h[p].x, h[p].y, h0, l0);
                cvt_hl(h[p].z, h[p].w, h1, l1);
                uint32_t off = ab + (16 * p) * RS;
                *(uint2*)(smem + off)        = make_uint2(h0, h1);
                *(uint2*)(smem + A_LO + off) = make_uint2(l0, l1);
            }
            if (c + 2 < NCH) {        /* refill regs for chunk c+2 */
                const float* np = hp + (c + 2) * KCH;
#pragma unroll
                for (int p = 0; p < 8; p++)
                    h[p] = __ldg((const float4*)(np + (size_t)16 * p * HID));
            }
        }
    }

    /* ---------------- epilogue: logits -> smem ---------------------- */
    __syncthreads();
    float* lg = (float*)smem;             /* 128 rows x 72 floats */
    {
        int er = R + (lane >> 2), ec = 2 * (lane & 3);
#pragma unroll
        for (int j = 0; j < 8; j++) {
            *(float2*)&lg[er * 72 + 8 * j + ec]       = make_float2(acc[4*j],   acc[4*j+1]);
            *(float2*)&lg[(er + 8) * 72 + 8 * j + ec] = make_float2(acc[4*j+2], acc[4*j+3]);
        }
    }
    __syncthreads();

    double da = 0.0, dz = 0.0;
    if (tid < TM) {
        float l[64];
#pragma unroll
        for (int g = 0; g < 16; g++)
            *(float4*)&l[4 * g] = *(float4*)&lg[tid * 72 + 4 * g];

        float m = l[0];
#pragma unroll
        for (int j = 1; j < 64; j++) m = fmaxf(m, l[j]);
        float ssum = 0.f;
#pragma unroll
        for (int j = 0; j < 64; j++) { l[j] = __expf(l[j] - m); ssum += l[j]; }
        float inv = 1.f / ssum;
        float lse = m + __logf(ssum);

        float v1 = -1.f, v2 = -1.f, sq = 0.f;
        int i1 = 0, i2 = 0;
#pragma unroll
        for (int j = 0; j < 64; j++) {
            float p = l[j];
            sq += p * p;
            if (p > v1)      { v2 = v1; i2 = i1; v1 = p; i1 = j; }
            else if (p > v2) { v2 = p; i2 = j; }
        }
        sq *= inv * inv;

        const int token = base + tid;
#pragma unroll
        for (int g = 0; g < 16; g++) {
            float4 o = make_float4(l[4*g] * inv, l[4*g+1] * inv,
                                   l[4*g+2] * inv, l[4*g+3] * inv);
            *(float4*)&probs[(size_t)token * 64 + 4 * g] = o;
        }
        float wsum = v1 + v2;
        *(int2*)&g_sidx[token * 2]   = make_int2(i1, i2);
        *(float2*)&g_sw[token * 2]   = make_float2(v1 / wsum, v2 / wsum);

        da = (double)sq;
        dz = (double)lse * (double)lse;
    }

#pragma unroll
    for (int off = 16; off; off >>= 1) {
        da += __shfl_xor_sync(0xffffffffu, da, off);
        dz += __shfl_xor_sync(0xffffffffu, dz, off);
    }
    __syncthreads();
    double* red = (double*)smem;
    if (lane == 0) { red[wid] = da; red[8 + wid] = dz; }
    __syncthreads();
    if (tid == 0) {
        double a = 0.0, z = 0.0;
#pragma unroll
        for (int i = 0; i < 8; i++) { a += red[i]; z += red[8 + i]; }
        atomicAdd(&g_acc[0], a);
        atomicAdd(&g_acc[1], z);
    }
}

/* ====== K3: capacity dispatch — smem-staged ballot rank scan ======== */
__global__ void __launch_bounds__(128)
dispatch_kernel(float* __restrict__ dispatch,
                float* __restrict__ combine,
                float* __restrict__ losses) {
    extern __shared__ int ds[];            /* [8192] idx + [8192] sw = 64 KB */
    const unsigned FULL = 0xffffffffu;
    const int tid = threadIdx.x;
    const int lane = tid & 31, wid = tid >> 5;
    const int b = blockIdx.x >> 4;
    const int e = ((blockIdx.x & 15) << 2) + wid;

    {
        const int4* si = (const int4*)&g_sidx[b * SEQ * TOPK];
        const int4* sw = (const int4*)&g_sw[b * SEQ * TOPK];
        int4* di = (int4*)ds;
        int4* dw = (int4*)(ds + SEQ * TOPK);
#pragma unroll
        for (int p = 0; p < 16; p++) { di[tid + 128 * p] = si[tid + 128 * p];
                                       dw[tid + 128 * p] = sw[tid + 128 * p]; }
    }
    __syncthreads();
    const float* swp = (const float*)(ds + SEQ * TOPK);
    unsigned lt = (1u << lane) - 1u;
    int cnt = 0;

#pragma unroll
    for (int k = 0; k < TOPK; k++) {
        for (int s0 = 0; s0 < SEQ; s0 += 256) {
            int vv[8];
#pragma unroll
            for (int u = 0; u < 8; u++) vv[u] = ds[(s0 + u * 32 + lane) * 2 + k];
#pragma unroll
            for (int u = 0; u < 8; u++) {
                unsigned msk = __ballot_sync(FULL, vv[u] == e);
                if (vv[u] == e) {
                    int r = cnt + __popc(msk & lt);
                    if (r < CAP) {
                        int sl = s0 + u * 32 + lane;
                        size_t o = (size_t)(b * SEQ + sl) * 64 + e;
                        dispatch[o] = 1.0f;
                        combine[o]  = swp[sl * 2 + k];
                    }
                }
                cnt += __popc(msk);
            }
        }
    }

    if (blockIdx.x == 0 && tid == 0) {     /* g_acc finalized by K1 */
        losses[0] = (float)(g_acc[0] * ((double)NUM_EXPERTS / (double)M_TOKENS));
        losses[1] = (float)(g_acc[1] / (double)M_TOKENS);
    }
}

/* ============================ launch ================================ */
extern "C" void kernel_launch(void* const* d_in, const int* in_sizes, int n_in,
                              void* d_out, int out_size) {
    const float* hidden = (const float*)d_in[0];
    const float* weight = (const float*)d_in[1];
    if (n_in >= 2 && in_sizes[0] < in_sizes[1]) {
        hidden = (const float*)d_in[1];
        weight = (const float*)d_in[0];
    }
    float* out      = (float*)d_out;
    float* dispatch = out;
    float* combine  = out + BSE;
    float* probs    = out + 2 * BSE;
    float* losses   = out + 3 * BSE;

    cudaFuncSetAttribute(gemm_kernel,
                         cudaFuncAttributeMaxDynamicSharedMemorySize, SMEM_GEMM);
    cudaFuncSetAttribute(dispatch_kernel,
                         cudaFuncAttributeMaxDynamicSharedMemorySize, 65536);

    prep_kernel<<<2048, 256>>>(weight, (float4*)out);
    gemm_kernel<<<M_TOKENS / TM, 256, SMEM_GEMM>>>(hidden, probs);
    dispatch_kernel<<<128, 128, 65536>>>(dispatch, combine, losses);
}

// round 11
// speedup vs baseline: 1.5528x; 1.5528x over previous
#include <cuda_runtime.h>
#include <cuda_bf16.h>
#include <cstdint>

#define NUM_EXPERTS 64
#define TOPK 2
#define CAP 128
#define BATCH 8
#define SEQ 4096
#define HID 4096
#define M_TOKENS (BATCH * SEQ)                 /* 32768 */
#define BSE ((size_t)M_TOKENS * NUM_EXPERTS)   /* 2097152 */

/* ------------ device scratch (static, allocation-free) ------------- */
__device__ int             g_sidx[M_TOKENS * TOPK];
__device__ float           g_sw[M_TOKENS * TOPK];
__device__ double          g_acc[2];                 /* aux, z */
__device__ __nv_bfloat16   g_whi[NUM_EXPERTS * HID];
__device__ __nv_bfloat16   g_wlo[NUM_EXPERTS * HID];

/* ---------------------- helpers ------------------------------------ */
__device__ __forceinline__ uint32_t smem_u32(const void* p) {
    uint32_t a;
    asm("{ .reg .u64 t; cvta.to.shared.u64 t, %1; cvt.u32.u64 %0, t; }"
        : "=r"(a) : "l"(p));
    return a;
}
__device__ __forceinline__ void ldsm4(uint32_t* r, uint32_t addr) {
    asm volatile("ldmatrix.sync.aligned.m8n8.x4.shared.b16 {%0,%1,%2,%3}, [%4];"
        : "=r"(r[0]), "=r"(r[1]), "=r"(r[2]), "=r"(r[3]) : "r"(addr));
}
__device__ __forceinline__ void mma_bf16(float* d, const uint32_t* a,
                                         uint32_t b0, uint32_t b1) {
    asm volatile(
        "mma.sync.aligned.m16n8k16.row.col.f32.bf16.bf16.f32 "
        "{%0,%1,%2,%3}, {%4,%5,%6,%7}, {%8,%9}, {%0,%1,%2,%3};"
        : "+f"(d[0]), "+f"(d[1]), "+f"(d[2]), "+f"(d[3])
        : "r"(a[0]), "r"(a[1]), "r"(a[2]), "r"(a[3]), "r"(b0), "r"(b1));
}
__device__ __forceinline__ void cp16(uint32_t dst, const void* src) {
    asm volatile("cp.async.cg.shared.global [%0], [%1], 16;"
                 :: "r"(dst), "l"(src) : "memory");
}
__device__ __forceinline__ void cvt_hl(float a, float b, uint32_t& h, uint32_t& l) {
    __nv_bfloat162 hh = __float22bfloat162_rn(make_float2(a, b));
    float2 hf = __bfloat1622float2(hh);
    __nv_bfloat162 ll = __float22bfloat162_rn(make_float2(a - hf.x, b - hf.y));
    h = *(uint32_t*)&hh;
    l = *(uint32_t*)&ll;
}

/* ============ K0: zero dispatch/combine + split weights ============= */
__global__ void prep_kernel(const float* __restrict__ w, float4* dc) {
    int t = blockIdx.x * 256 + threadIdx.x;           /* grid 2048 */
    const size_t n4 = (2 * BSE) / 4;
    float4 z = make_float4(0.f, 0.f, 0.f, 0.f);
    for (size_t j = t; j < n4; j += 2048 * 256) dc[j] = z;
    int i0 = t * 2;
    if (i0 < NUM_EXPERTS * HID) {
#pragma unroll
        for (int u = 0; u < 2; u++) {
            int i = i0 + u;
            float x = w[i];
            __nv_bfloat16 h = __float2bfloat16(x);
            g_whi[i] = h;
            g_wlo[i] = __float2bfloat16(x - __bfloat162float(h));
        }
    }
    if (t == 0) { g_acc[0] = 0.0; g_acc[1] = 0.0; }
}

/* ===== K1: HMMA bf16-split GEMM + fused softmax/top2/losses ========= */
/* (Round-6 measured-best configuration, verbatim.)
 * CTA: 128 tokens x 64 experts, 8 warps (16 rows each), K-chunk 64.   */
#define TM 128
#define KCH 64
#define NCHUNK (HID / KCH)
#define RS 144                     /* bytes per 64-bf16 row, padded    */
#define OFF_AL 18432               /* 128*144                          */
#define OFF_W  36864
#define W_LO   9216                /* 64*144                           */
#define W_BUF  18432
#define SMEM_GEMM (OFF_W + 2 * W_BUF)   /* 73728 */

__device__ __forceinline__ void cp_w(uint32_t wb, int k0, int wrow, int wkq) {
    const __nv_bfloat16* gh = g_whi + (size_t)wrow * HID + k0 + 16 * wkq;
    const __nv_bfloat16* gl = g_wlo + (size_t)wrow * HID + k0 + 16 * wkq;
    uint32_t off = wrow * RS + 32 * wkq;
    cp16(wb + off,             gh);
    cp16(wb + off + 16,        gh + 8);
    cp16(wb + W_LO + off,      gl);
    cp16(wb + W_LO + off + 16, gl + 8);
}

__global__ void __launch_bounds__(256, 2)
gemm_kernel(const float* __restrict__ hidden, float* __restrict__ probs) {
    extern __shared__ char smem[];
    const uint32_t sb = smem_u32(smem);
    const int tid = threadIdx.x;
    const int lane = tid & 31, wid = tid >> 5;
    const int base = blockIdx.x * TM;
    const int R = wid * 16;

    float acc[32];
#pragma unroll
    for (int i = 0; i < 32; i++) acc[i] = 0.f;

    const int hrow = tid >> 4, hkq = tid & 15;       /* hidden ldg map  */
    const int wrow = tid >> 2, wkq = tid & 3;        /* weight cp map   */

    float4 h[8];
    {
        const float* hp = hidden + (size_t)(base + hrow) * HID + 4 * hkq;
#pragma unroll
        for (int p = 0; p < 8; p++)
            h[p] = __ldg((const float4*)(hp + (size_t)16 * p * HID));
        cp_w(sb + OFF_W, 0, wrow, wkq);
        asm volatile("cp.async.commit_group;" ::: "memory");
    }

    /* ldmatrix source addresses (per-lane, chunk-invariant parts) */
    const uint32_t aH = sb + (R + (lane & 15)) * RS + 16 * (lane >> 4);
    const uint32_t aL = aH + OFF_AL;
    const uint32_t bC = sb + OFF_W + (8 * (lane >> 4) + (lane & 7)) * RS
                        + 16 * ((lane >> 3) & 1);

    for (int c = 0; c < NCHUNK; c++) {
        const int s = c & 1;
        __syncthreads();                      /* prior MMA done with stage */
#pragma unroll
        for (int p = 0; p < 8; p++) {
            int row = hrow + 16 * p;
            uint32_t hi0, lo0, hi1, lo1;
            cvt_hl(h[p].x, h[p].y, hi0, lo0);
            cvt_hl(h[p].z, h[p].w, hi1, lo1);
            uint32_t off = row * RS + 8 * hkq;
            *(uint2*)(smem + off)          = make_uint2(hi0, hi1);
            *(uint2*)(smem + OFF_AL + off) = make_uint2(lo0, lo1);
        }
        asm volatile("cp.async.wait_group 0;" ::: "memory");
        __syncthreads();                      /* stage + weights visible   */

        if (c + 1 < NCHUNK) {                 /* prefetch, overlaps MMA    */
            const float* hp = hidden + (size_t)(base + hrow) * HID
                              + (c + 1) * KCH + 4 * hkq;
#pragma unroll
            for (int p = 0; p < 8; p++)
                h[p] = __ldg((const float4*)(hp + (size_t)16 * p * HID));
            cp_w(sb + OFF_W + ((c + 1) & 1) * W_BUF, (c + 1) * KCH, wrow, wkq);
            asm volatile("cp.async.commit_group;" ::: "memory");
        }

        const uint32_t bS = bC + s * W_BUF;
#pragma unroll
        for (int q = 0; q < 4; q++) {
            uint32_t ah[4], al[4];
            ldsm4(ah, aH + 32 * q);
            ldsm4(al, aL + 32 * q);
#pragma unroll
            for (int jp = 0; jp < 4; jp++) {
                uint32_t bh[4], bl[4];
                ldsm4(bh, bS + jp * (16 * RS) + 32 * q);
                ldsm4(bl, bS + W_LO + jp * (16 * RS) + 32 * q);
                mma_bf16(acc + 8 * jp,     ah, bh[0], bh[1]);
                mma_bf16(acc + 8 * jp,     ah, bl[0], bl[1]);
                mma_bf16(acc + 8 * jp,     al, bh[0], bh[1]);
                mma_bf16(acc + 8 * jp + 4, ah, bh[2], bh[3]);
                mma_bf16(acc + 8 * jp + 4, ah, bl[2], bl[3]);
                mma_bf16(acc + 8 * jp + 4, al, bh[2], bh[3]);
            }
        }
    }

    /* ---------------- epilogue: logits -> smem ---------------------- */
    __syncthreads();                          /* all warps done with A     */
    float* lg = (float*)smem;                 /* 128 rows x 72-float rows  */
    {
        int er = R + (lane >> 2), ec = 2 * (lane & 3);
#pragma unroll
        for (int j = 0; j < 8; j++) {
            *(float2*)&lg[er * 72 + 8 * j + ec]       = make_float2(acc[4*j],   acc[4*j+1]);
            *(float2*)&lg[(er + 8) * 72 + 8 * j + ec] = make_float2(acc[4*j+2], acc[4*j+3]);
        }
    }
    __syncthreads();

    double da = 0.0, dz = 0.0;
    if (tid < TM) {
        float l[64];
#pragma unroll
        for (int g = 0; g < 16; g++)
            *(float4*)&l[4 * g] = *(float4*)&lg[tid * 72 + 4 * g];

        float m = l[0];
#pragma unroll
        for (int j = 1; j < 64; j++) m = fmaxf(m, l[j]);
        float ssum = 0.f;
#pragma unroll
        for (int j = 0; j < 64; j++) { l[j] = __expf(l[j] - m); ssum += l[j]; }
        float inv = 1.f / ssum;
        float lse = m + __logf(ssum);

        float v1 = -1.f, v2 = -1.f, sq = 0.f;
        int i1 = 0, i2 = 0;
#pragma unroll
        for (int j = 0; j < 64; j++) {
            float p = l[j];
            sq += p * p;
            if (p > v1)      { v2 = v1; i2 = i1; v1 = p; i1 = j; }
            else if (p > v2) { v2 = p; i2 = j; }
        }
        sq *= inv * inv;

        const int token = base + tid;
#pragma unroll
        for (int g = 0; g < 16; g++) {
            float4 v = make_float4(l[4*g] * inv, l[4*g+1] * inv,
                                   l[4*g+2] * inv, l[4*g+3] * inv);
            *(float4*)&probs[(size_t)token * 64 + 4 * g] = v;
        }
        float wsum = v1 + v2;
        *(int2*)&g_sidx[token * 2]   = make_int2(i1, i2);
        *(float2*)&g_sw[token * 2]   = make_float2(v1 / wsum, v2 / wsum);

        da = (double)sq;
        dz = (double)lse * (double)lse;
    }

#pragma unroll
    for (int off = 16; off; off >>= 1) {
        da += __shfl_xor_sync(0xffffffffu, da, off);
        dz += __shfl_xor_sync(0xffffffffu, dz, off);
    }
    __syncthreads();
    double* red = (double*)(smem + OFF_W);    /* W region idle now */
    if (lane == 0) { red[wid] = da; red[8 + wid] = dz; }
    __syncthreads();
    if (tid == 0) {
        double a = 0.0, z = 0.0;
#pragma unroll
        for (int i = 0; i < 8; i++) { a += red[i]; z += red[8 + i]; }
        atomicAdd(&g_acc[0], a);
        atomicAdd(&g_acc[1], z);
    }
}

/* ====== K3: capacity dispatch — smem-staged ballot rank scan ======== */
/* 128 blocks x 128 thr: block = (batch, expert-group of 4), 1 warp/e. */
__global__ void __launch_bounds__(128)
dispatch_kernel(float* __restrict__ dispatch,
                float* __restrict__ combine,
                float* __restrict__ losses) {
    extern __shared__ int ds[];            /* [8192] idx + [8192] sw = 64 KB */
    const unsigned FULL = 0xffffffffu;
    const int tid = threadIdx.x;
    const int lane = tid & 31, wid = tid >> 5;
    const int b = blockIdx.x >> 4;
    const int e = ((blockIdx.x & 15) << 2) + wid;

    {
        const int4* si = (const int4*)&g_sidx[b * SEQ * TOPK];
        const int4* sw = (const int4*)&g_sw[b * SEQ * TOPK];
        int4* di = (int4*)ds;
        int4* dw = (int4*)(ds + SEQ * TOPK);
#pragma unroll
        for (int p = 0; p < 16; p++) { di[tid + 128 * p] = si[tid + 128 * p];
                                       dw[tid + 128 * p] = sw[tid + 128 * p]; }
    }
    __syncthreads();
    const float* swp = (const float*)(ds + SEQ * TOPK);
    unsigned lt = (1u << lane) - 1u;
    int cnt = 0;

#pragma unroll
    for (int k = 0; k < TOPK; k++) {
        for (int s0 = 0; s0 < SEQ; s0 += 256) {
            int vv[8];
#pragma unroll
            for (int u = 0; u < 8; u++) vv[u] = ds[(s0 + u * 32 + lane) * 2 + k];
#pragma unroll
            for (int u = 0; u < 8; u++) {
                unsigned msk = __ballot_sync(FULL, vv[u] == e);
                if (vv[u] == e) {
                    int r = cnt + __popc(msk & lt);
                    if (r < CAP) {
                        int sl = s0 + u * 32 + lane;
                        size_t o = (size_t)(b * SEQ + sl) * 64 + e;
                        dispatch[o] = 1.0f;
                        combine[o]  = swp[sl * 2 + k];
                    }
                }
                cnt += __popc(msk);
            }
        }
    }

    if (blockIdx.x == 0 && tid == 0) {     /* g_acc finalized by K1 */
        losses[0] = (float)(g_acc[0] * ((double)NUM_EXPERTS / (double)M_TOKENS));
        losses[1] = (float)(g_acc[1] / (double)M_TOKENS);
    }
}

/* ============================ launch ================================ */
extern "C" void kernel_launch(void* const* d_in, const int* in_sizes, int n_in,
                              void* d_out, int out_size) {
    const float* hidden = (const float*)d_in[0];
    const float* weight = (const float*)d_in[1];
    if (n_in >= 2 && in_sizes[0] < in_sizes[1]) {
        hidden = (const float*)d_in[1];
        weight = (const float*)d_in[0];
    }
    float* out      = (float*)d_out;
    float* dispatch = out;
    float* combine  = out + BSE;
    float* probs    = out + 2 * BSE;
    float* losses   = out + 3 * BSE;

    cudaFuncSetAttribute(gemm_kernel,
                         cudaFuncAttributeMaxDynamicSharedMemorySize, SMEM_GEMM);
    cudaFuncSetAttribute(dispatch_kernel,
                         cudaFuncAttributeMaxDynamicSharedMemorySize, 65536);

    prep_kernel<<<2048, 256>>>(weight, (float4*)out);
    gemm_kernel<<<M_TOKENS / TM, 256, SMEM_GEMM>>>(hidden, probs);
    dispatch_kernel<<<128, 128, 65536>>>(dispatch, combine, losses);
}

// round 14
// speedup vs baseline: 1.6138x; 1.0393x over previous
#include <cuda_runtime.h>
#include <cuda_bf16.h>
#include <cstdint>

#define NUM_EXPERTS 64
#define TOPK 2
#define CAP 128
#define BATCH 8
#define SEQ 4096
#define HID 4096
#define M_TOKENS (BATCH * SEQ)                 /* 32768 */
#define BSE ((size_t)M_TOKENS * NUM_EXPERTS)   /* 2097152 */

/* ------------ device scratch (static, allocation-free) ------------- */
__device__ int             g_sidx[M_TOKENS * TOPK];
__device__ float           g_sw[M_TOKENS * TOPK];
__device__ double          g_acc[2];                 /* aux, z */
__device__ __nv_bfloat16   g_whi[NUM_EXPERTS * HID];
__device__ __nv_bfloat16   g_wlo[NUM_EXPERTS * HID];

/* ---------------------- helpers ------------------------------------ */
__device__ __forceinline__ uint32_t smem_u32(const void* p) {
    uint32_t a;
    asm("{ .reg .u64 t; cvta.to.shared.u64 t, %1; cvt.u32.u64 %0, t; }"
        : "=r"(a) : "l"(p));
    return a;
}
__device__ __forceinline__ void ldsm4(uint32_t* r, uint32_t addr) {
    asm volatile("ldmatrix.sync.aligned.m8n8.x4.shared.b16 {%0,%1,%2,%3}, [%4];"
        : "=r"(r[0]), "=r"(r[1]), "=r"(r[2]), "=r"(r[3]) : "r"(addr));
}
__device__ __forceinline__ void mma_bf16(float* d, const uint32_t* a,
                                         uint32_t b0, uint32_t b1) {
    asm volatile(
        "mma.sync.aligned.m16n8k16.row.col.f32.bf16.bf16.f32 "
        "{%0,%1,%2,%3}, {%4,%5,%6,%7}, {%8,%9}, {%0,%1,%2,%3};"
        : "+f"(d[0]), "+f"(d[1]), "+f"(d[2]), "+f"(d[3])
        : "r"(a[0]), "r"(a[1]), "r"(a[2]), "r"(a[3]), "r"(b0), "r"(b1));
}
__device__ __forceinline__ void cp16(uint32_t dst, const void* src) {
    asm volatile("cp.async.cg.shared.global [%0], [%1], 16;"
                 :: "r"(dst), "l"(src) : "memory");
}
__device__ __forceinline__ void cvt_hl(float a, float b, uint32_t& h, uint32_t& l) {
    __nv_bfloat162 hh = __float22bfloat162_rn(make_float2(a, b));
    float2 hf = __bfloat1622float2(hh);
    __nv_bfloat162 ll = __float22bfloat162_rn(make_float2(a - hf.x, b - hf.y));
    h = *(uint32_t*)&hh;
    l = *(uint32_t*)&ll;
}

/* ============ K0: zero dispatch/combine + split weights ============= */
__global__ void prep_kernel(const float* __restrict__ w, float4* dc) {
    int t = blockIdx.x * 256 + threadIdx.x;           /* grid 2048 */
    const size_t n4 = (2 * BSE) / 4;
    float4 z = make_float4(0.f, 0.f, 0.f, 0.f);
    for (size_t j = t; j < n4; j += 2048 * 256) dc[j] = z;
    int i0 = t * 2;
    if (i0 < NUM_EXPERTS * HID) {
#pragma unroll
        for (int u = 0; u < 2; u++) {
            int i = i0 + u;
            float x = w[i];
            __nv_bfloat16 h = __float2bfloat16(x);
            g_whi[i] = h;
            g_wlo[i] = __float2bfloat16(x - __bfloat162float(h));
        }
    }
    if (t == 0) { g_acc[0] = 0.0; g_acc[1] = 0.0; }
}

/* ===== K1: HMMA bf16-split GEMM + fused softmax/top2/losses ========= */
/* R6 skeleton; ONLY the warp tile changed: (16,64) -> (32,32).
 * 8 warps = 4 row-groups x 2 expert-groups.  B ldsm traffic halved.   */
#define TM 128
#define KCH 64
#define NCHUNK (HID / KCH)
#define RS 144                     /* bytes per 64-bf16 row, padded    */
#define OFF_AL 18432               /* 128*144                          */
#define OFF_W  36864
#define W_LO   9216                /* 64*144                           */
#define W_BUF  18432
#define SMEM_GEMM (OFF_W + 2 * W_BUF)   /* 73728 */

__device__ __forceinline__ void cp_w(uint32_t wb, int k0, int wrow, int wkq) {
    const __nv_bfloat16* gh = g_whi + (size_t)wrow * HID + k0 + 16 * wkq;
    const __nv_bfloat16* gl = g_wlo + (size_t)wrow * HID + k0 + 16 * wkq;
    uint32_t off = wrow * RS + 32 * wkq;
    cp16(wb + off,             gh);
    cp16(wb + off + 16,        gh + 8);
    cp16(wb + W_LO + off,      gl);
    cp16(wb + W_LO + off + 16, gl + 8);
}

__global__ void __launch_bounds__(256, 2)
gemm_kernel(const float* __restrict__ hidden, float* __restrict__ probs) {
    extern __shared__ char smem[];
    const uint32_t sb = smem_u32(smem);
    const int tid = threadIdx.x;
    const int lane = tid & 31, wid = tid >> 5;
    const int base = blockIdx.x * TM;
    const int R = (wid & 3) * 32;          /* warp rows   R..R+31  */
    const int E = (wid >> 2) * 32;         /* warp experts E..E+31 */

    float acc[32];                          /* [mt][jp][8] = 2*2*8 */
#pragma unroll
    for (int i = 0; i < 32; i++) acc[i] = 0.f;

    const int hrow = tid >> 4, hkq = tid & 15;       /* hidden ldg map  */
    const int wrow = tid >> 2, wkq = tid & 3;        /* weight cp map   */

    float4 h[8];
    {
        const float* hp = hidden + (size_t)(base + hrow) * HID + 4 * hkq;
#pragma unroll
        for (int p = 0; p < 8; p++)
            h[p] = __ldg((const float4*)(hp + (size_t)16 * p * HID));
        cp_w(sb + OFF_W, 0, wrow, wkq);
        asm volatile("cp.async.commit_group;" ::: "memory");
    }

    /* ldmatrix per-lane bases */
    const uint32_t aM0 = sb + (R + (lane & 15)) * RS + 16 * (lane >> 4);
    const uint32_t aM1 = aM0 + 16 * RS;
    const uint32_t bC  = sb + OFF_W
                         + (E + 8 * (lane >> 4) + (lane & 7)) * RS
                         + 16 * ((lane >> 3) & 1);

    for (int c = 0; c < NCHUNK; c++) {
        const int s = c & 1;
        __syncthreads();                      /* prior MMA done with stage */
#pragma unroll
        for (int p = 0; p < 8; p++) {
            int row = hrow + 16 * p;
            uint32_t hi0, lo0, hi1, lo1;
            cvt_hl(h[p].x, h[p].y, hi0, lo0);
            cvt_hl(h[p].z, h[p].w, hi1, lo1);
            uint32_t off = row * RS + 8 * hkq;
            *(uint2*)(smem + off)          = make_uint2(hi0, hi1);
            *(uint2*)(smem + OFF_AL + off) = make_uint2(lo0, lo1);
        }
        asm volatile("cp.async.wait_group 0;" ::: "memory");
        __syncthreads();                      /* stage + weights visible   */

        if (c + 1 < NCHUNK) {                 /* prefetch, overlaps MMA    */
            const float* hp = hidden + (size_t)(base + hrow) * HID
                              + (c + 1) * KCH + 4 * hkq;
#pragma unroll
            for (int p = 0; p < 8; p++)
                h[p] = __ldg((const float4*)(hp + (size_t)16 * p * HID));
            cp_w(sb + OFF_W + ((c + 1) & 1) * W_BUF, (c + 1) * KCH, wrow, wkq);
            asm volatile("cp.async.commit_group;" ::: "memory");
        }

        const uint32_t bS = bC + s * W_BUF;
#pragma unroll
        for (int q = 0; q < 4; q++) {
            uint32_t ah[2][4], al[2][4];
            ldsm4(ah[0], aM0 + 32 * q);
            ldsm4(al[0], aM0 + OFF_AL + 32 * q);
            ldsm4(ah[1], aM1 + 32 * q);
            ldsm4(al[1], aM1 + OFF_AL + 32 * q);
#pragma unroll
            for (int jp = 0; jp < 2; jp++) {
                uint32_t bh[4], bl[4];
                ldsm4(bh, bS + jp * (16 * RS) + 32 * q);
                ldsm4(bl, bS + W_LO + jp * (16 * RS) + 32 * q);
#pragma unroll
                for (int mt = 0; mt < 2; mt++) {
                    float* d = acc + mt * 16 + jp * 8;
                    mma_bf16(d,     ah[mt], bh[0], bh[1]);
                    mma_bf16(d,     ah[mt], bl[0], bl[1]);
                    mma_bf16(d,     al[mt], bh[0], bh[1]);
                    mma_bf16(d + 4, ah[mt], bh[2], bh[3]);
                    mma_bf16(d + 4, ah[mt], bl[2], bl[3]);
                    mma_bf16(d + 4, al[mt], bh[2], bh[3]);
                }
            }
        }
    }

    /* ---------------- epilogue: logits -> smem ---------------------- */
    __syncthreads();                          /* all warps done with A     */
    float* lg = (float*)smem;                 /* 128 rows x 72-float rows  */
    {
        int er0 = R + (lane >> 2), ec = 2 * (lane & 3);
#pragma unroll
        for (int mt = 0; mt < 2; mt++) {
#pragma unroll
            for (int jp = 0; jp < 2; jp++) {
                float* d = acc + mt * 16 + jp * 8;
                int er = er0 + 16 * mt;
                int c0 = E + jp * 16 + ec;
                *(float2*)&lg[er * 72 + c0]           = make_float2(d[0], d[1]);
                *(float2*)&lg[(er + 8) * 72 + c0]     = make_float2(d[2], d[3]);
                *(float2*)&lg[er * 72 + c0 + 8]       = make_float2(d[4], d[5]);
                *(float2*)&lg[(er + 8) * 72 + c0 + 8] = make_float2(d[6], d[7]);
            }
        }
    }
    __syncthreads();

    double da = 0.0, dz = 0.0;
    if (tid < TM) {
        float l[64];
#pragma unroll
        for (int g = 0; g < 16; g++)
            *(float4*)&l[4 * g] = *(float4*)&lg[tid * 72 + 4 * g];

        float m = l[0];
#pragma unroll
        for (int j = 1; j < 64; j++) m = fmaxf(m, l[j]);
        float ssum = 0.f;
#pragma unroll
        for (int j = 0; j < 64; j++) { l[j] = __expf(l[j] - m); ssum += l[j]; }
        float inv = 1.f / ssum;
        float lse = m + __logf(ssum);

        float v1 = -1.f, v2 = -1.f, sq = 0.f;
        int i1 = 0, i2 = 0;
#pragma unroll
        for (int j = 0; j < 64; j++) {
            float p = l[j];
            sq += p * p;
            if (p > v1)      { v2 = v1; i2 = i1; v1 = p; i1 = j; }
            else if (p > v2) { v2 = p; i2 = j; }
        }
        sq *= inv * inv;

        const int token = base + tid;
#pragma unroll
        for (int g = 0; g < 16; g++) {
            float4 v = make_float4(l[4*g] * inv, l[4*g+1] * inv,
                                   l[4*g+2] * inv, l[4*g+3] * inv);
            *(float4*)&probs[(size_t)token * 64 + 4 * g] = v;
        }
        float wsum = v1 + v2;
        *(int2*)&g_sidx[token * 2]   = make_int2(i1, i2);
        *(float2*)&g_sw[token * 2]   = make_float2(v1 / wsum, v2 / wsum);

        da = (double)sq;
        dz = (double)lse * (double)lse;
    }

#pragma unroll
    for (int off = 16; off; off >>= 1) {
        da += __shfl_xor_sync(0xffffffffu, da, off);
        dz += __shfl_xor_sync(0xffffffffu, dz, off);
    }
    __syncthreads();
    double* red = (double*)(smem + OFF_W);    /* W region idle now */
    if (lane == 0) { red[wid] = da; red[8 + wid] = dz; }
    __syncthreads();
    if (tid == 0) {
        double a = 0.0, z = 0.0;
#pragma unroll
        for (int i = 0; i < 8; i++) { a += red[i]; z += red[8 + i]; }
        atomicAdd(&g_acc[0], a);
        atomicAdd(&g_acc[1], z);
    }
}

/* ====== K3: capacity dispatch — smem-staged ballot rank scan ======== */
/* 128 blocks x 128 thr: block = (batch, expert-group of 4), 1 warp/e. */
__global__ void __launch_bounds__(128)
dispatch_kernel(float* __restrict__ dispatch,
                float* __restrict__ combine,
                float* __restrict__ losses) {
    extern __shared__ int ds[];            /* [8192] idx + [8192] sw = 64 KB */
    const unsigned FULL = 0xffffffffu;
    const int tid = threadIdx.x;
    const int lane = tid & 31, wid = tid >> 5;
    const int b = blockIdx.x >> 4;
    const int e = ((blockIdx.x & 15) << 2) + wid;

    {
        const int4* si = (const int4*)&g_sidx[b * SEQ * TOPK];
        const int4* sw = (const int4*)&g_sw[b * SEQ * TOPK];
        int4* di = (int4*)ds;
        int4* dw = (int4*)(ds + SEQ * TOPK);
#pragma unroll
        for (int p = 0; p < 16; p++) { di[tid + 128 * p] = si[tid + 128 * p];
                                       dw[tid + 128 * p] = sw[tid + 128 * p]; }
    }
    __syncthreads();
    const float* swp = (const float*)(ds + SEQ * TOPK);
    unsigned lt = (1u << lane) - 1u;
    int cnt = 0;

#pragma unroll
    for (int k = 0; k < TOPK; k++) {
        for (int s0 = 0; s0 < SEQ; s0 += 256) {
            int vv[8];
#pragma unroll
            for (int u = 0; u < 8; u++) vv[u] = ds[(s0 + u * 32 + lane) * 2 + k];
#pragma unroll
            for (int u = 0; u < 8; u++) {
                unsigned msk = __ballot_sync(FULL, vv[u] == e);
                if (vv[u] == e) {
                    int r = cnt + __popc(msk & lt);
                    if (r < CAP) {
                        int sl = s0 + u * 32 + lane;
                        size_t o = (size_t)(b * SEQ + sl) * 64 + e;
                        dispatch[o] = 1.0f;
                        combine[o]  = swp[sl * 2 + k];
                    }
                }
                cnt += __popc(msk);
            }
        }
    }

    if (blockIdx.x == 0 && tid == 0) {     /* g_acc finalized by K1 */
        losses[0] = (float)(g_acc[0] * ((double)NUM_EXPERTS / (double)M_TOKENS));
        losses[1] = (float)(g_acc[1] / (double)M_TOKENS);
    }
}

/* ============================ launch ================================ */
extern "C" void kernel_launch(void* const* d_in, const int* in_sizes, int n_in,
                              void* d_out, int out_size) {
    const float* hidden = (const float*)d_in[0];
    const float* weight = (const float*)d_in[1];
    if (n_in >= 2 && in_sizes[0] < in_sizes[1]) {
        hidden = (const float*)d_in[1];
        weight = (const float*)d_in[0];
    }
    float* out      = (float*)d_out;
    float* dispatch = out;
    float* combine  = out + BSE;
    float* probs    = out + 2 * BSE;
    float* losses   = out + 3 * BSE;

    cudaFuncSetAttribute(gemm_kernel,
                         cudaFuncAttributeMaxDynamicSharedMemorySize, SMEM_GEMM);
    cudaFuncSetAttribute(dispatch_kernel,
                         cudaFuncAttributeMaxDynamicSharedMemorySize, 65536);

    prep_kernel<<<2048, 256>>>(weight, (float4*)out);
    gemm_kernel<<<M_TOKENS / TM, 256, SMEM_GEMM>>>(hidden, probs);
    dispatch_kernel<<<128, 128, 65536>>>(dispatch, combine, losses);
}